// round 4
// baseline (speedup 1.0000x reference)
#include <cuda_runtime.h>
#include <cstdint>

// Problem constants
#define B_ROWS   4096
#define SEQ_L    128
#define EMB      128     // E
#define K2       256     // 2E
#define VOCAB    100000
#define OUT_N    3
#define DEPTH    7
#define ROWS_PB  2       // batch rows per block
#define NTHREADS 256

// Repacked W_tree: Wp[kp*256 + 2*e + r] = W_tree[e*256 + 2*kp + r]
// i.e. float2 at (kp, e) = (W[e][2kp], W[e][2kp+1])
__device__ float gWp[128 * 256];

__global__ void prep_wp_kernel(const float* __restrict__ W_tree) {
    int o = blockIdx.x * 256 + threadIdx.x;   // 0 .. 32767
    int kp  = o >> 8;
    int rem = o & 255;
    int e   = rem >> 1;
    int r   = rem & 1;
    gWp[o] = W_tree[e * 256 + 2 * kp + r];
}

// packed fp32x2 FMA (Blackwell): d = a*b + c elementwise on 2 packed floats
__device__ __forceinline__ float2 ffma2(float2 a, float2 b, float2 c) {
    unsigned long long ua, ub, uc, ud;
    ua = *reinterpret_cast<unsigned long long*>(&a);
    ub = *reinterpret_cast<unsigned long long*>(&b);
    uc = *reinterpret_cast<unsigned long long*>(&c);
    asm("fma.rn.f32x2 %0, %1, %2, %3;" : "=l"(ud) : "l"(ua), "l"(ub), "l"(uc));
    return *reinterpret_cast<float2*>(&ud);
}

// SMEM layout (floats):
//   sWp  [32768]  = 131072 B   (repacked W)
//   bufA [16384]  =  65536 B   (128 nodes x 128)
//   bufB [ 8192]  =  32768 B   ( 64 nodes x 128)
//   sb   [  128]  =    512 B   (b_tree)
// total = 229888 B  (< 232448 B sm_103a opt-in max)
#define SMEM_FLOATS (32768 + 16384 + 8192 + 128)
#define SMEM_BYTES  (SMEM_FLOATS * 4)

__global__ __launch_bounds__(NTHREADS, 1)
void tree_kernel(const int* __restrict__ tokens,
                 const float* __restrict__ embedding,
                 const float* __restrict__ b_tree,
                 const float* __restrict__ W_cls,
                 const float* __restrict__ b_cls,
                 float* __restrict__ out)
{
    extern __shared__ float smem[];
    float* sWp  = smem;
    float* bufA = smem + 32768;
    float* bufB = bufA + 16384;
    float* sb   = bufB + 8192;

    const int t = threadIdx.x;

    // --- Load repacked W into SMEM (conflict-free, vectorized) ---
    {
        float4* d4 = reinterpret_cast<float4*>(sWp);
        const float4* s4 = reinterpret_cast<const float4*>(gWp);
        #pragma unroll 8
        for (int i = t; i < 8192; i += NTHREADS) d4[i] = s4[i];
    }
    if (t < 128) sb[t] = b_tree[t];

    const int e  = t & 127;    // output feature this thread owns
    const int ng = t >> 7;     // node parity group (0/1)

    for (int r = 0; r < ROWS_PB; r++) {
        const int row = blockIdx.x * ROWS_PB + r;

        // --- Phase 1: embedding gather into bufA (128 leaves x 128) ---
        {
            float4* bA4 = reinterpret_cast<float4*>(bufA);
            const float4* emb4 = reinterpret_cast<const float4*>(embedding);
            const int* trow = tokens + row * SEQ_L;
            #pragma unroll 4
            for (int i = t; i < 4096; i += NTHREADS) {
                int leaf = i >> 5;          // 0..127
                int c4   = i & 31;          // float4 col
                int tok = trow[leaf];
                // branch-free clamp to valid range (insurance, not expected to fire)
                tok = min(max(tok, 0), VOCAB - 1);
                bA4[i] = emb4[(long long)tok * 32 + c4];
            }
        }
        __syncthreads();

        // --- Phase 2: 7 tree levels ---
        float* inb  = bufA;
        float* outb = bufB;
        int nodesOut = 64;
        const float2* w2base = reinterpret_cast<const float2*>(sWp);

        for (int lvl = 0; lvl < DEPTH; lvl++) {
            const float2* in2 = reinterpret_cast<const float2*>(inb);
            const float bb = sb[e];

            for (int nb = ng; nb < nodesOut; nb += 8) {
                // 4 nodes: nb, nb+2, nb+4, nb+6 (share W loads)
                const float2* x0 = in2 + (nb + 0) * 128;
                const float2* x1 = in2 + (nb + 2) * 128;
                const float2* x2 = in2 + (nb + 4) * 128;
                const float2* x3 = in2 + (nb + 6) * 128;

                float2 a0 = make_float2(0.f, 0.f);
                float2 a1 = make_float2(0.f, 0.f);
                float2 a2 = make_float2(0.f, 0.f);
                float2 a3 = make_float2(0.f, 0.f);

                #pragma unroll 4
                for (int kp = 0; kp < 128; kp++) {
                    float2 w = w2base[kp * 128 + e];
                    a0 = ffma2(x0[kp], w, a0);
                    a1 = ffma2(x1[kp], w, a1);
                    a2 = ffma2(x2[kp], w, a2);
                    a3 = ffma2(x3[kp], w, a3);
                }

                if (nb + 0 < nodesOut) outb[(nb + 0) * 128 + e] = tanhf(a0.x + a0.y + bb);
                if (nb + 2 < nodesOut) outb[(nb + 2) * 128 + e] = tanhf(a1.x + a1.y + bb);
                if (nb + 4 < nodesOut) outb[(nb + 4) * 128 + e] = tanhf(a2.x + a2.y + bb);
                if (nb + 6 < nodesOut) outb[(nb + 6) * 128 + e] = tanhf(a3.x + a3.y + bb);
            }
            __syncthreads();
            float* tmp = inb; inb = outb; outb = tmp;
            nodesOut >>= 1;
        }
        // After 7 swaps, root reps (128 floats) are at inb (== bufB).

        // --- Phase 3: classifier: out[row] = root @ W_cls^T + b_cls ---
        if (t < 96) {
            int j = t >> 5, lane = t & 31;
            const float* wrow = W_cls + j * 128;
            float p = inb[lane]       * wrow[lane]
                    + inb[lane + 32]  * wrow[lane + 32]
                    + inb[lane + 64]  * wrow[lane + 64]
                    + inb[lane + 96]  * wrow[lane + 96];
            #pragma unroll
            for (int off = 16; off; off >>= 1)
                p += __shfl_down_sync(0xffffffffu, p, off);
            if (lane == 0) out[row * OUT_N + j] = p + b_cls[j];
        }
        __syncthreads();   // protect bufB before next row's level-0 writes
    }
}

extern "C" void kernel_launch(void* const* d_in, const int* in_sizes, int n_in,
                              void* d_out, int out_size) {
    const int*   tokens    = (const int*)d_in[0];
    const float* embedding = (const float*)d_in[1];
    const float* W_tree    = (const float*)d_in[2];
    const float* b_tree    = (const float*)d_in[3];
    const float* W_cls     = (const float*)d_in[4];
    const float* b_cls     = (const float*)d_in[5];
    float*       out       = (float*)d_out;

    (void)in_sizes; (void)n_in; (void)out_size;

    // Repack W_tree once per launch (graph-capturable, same-stream ordered)
    prep_wp_kernel<<<128, 256>>>(W_tree);

    cudaFuncSetAttribute(tree_kernel,
                         cudaFuncAttributeMaxDynamicSharedMemorySize, SMEM_BYTES);

    tree_kernel<<<B_ROWS / ROWS_PB, NTHREADS, SMEM_BYTES>>>(
        tokens, embedding, b_tree, W_cls, b_cls, out);
}

// round 6
// speedup vs baseline: 1.4607x; 1.4607x over previous
#include <cuda_runtime.h>
#include <cstdint>

// Problem constants
#define B_ROWS   4096
#define SEQ_L    128
#define EMB      128     // E
#define VOCAB    100000
#define OUT_N    3
#define DEPTH    7
#define ROWS_PB  4       // batch rows per block
#define NTHREADS 512

// Repacked W_tree as float4 tiles:
// Wq[kp2*128 + e] = float4(W[e][4kp2], W[e][4kp2+1], W[e][4kp2+2], W[e][4kp2+3])
// kp2 = 0..63 (4-wide k chunks), e = 0..127
__device__ float gWq[128 * 256];

__global__ void prep_wq_kernel(const float* __restrict__ W_tree) {
    int o = blockIdx.x * 256 + threadIdx.x;   // 0 .. 32767
    int kp2 = o >> 9;          // 0..63
    int rem = o & 511;
    int e   = rem >> 2;        // 0..127
    int q   = rem & 3;         // 0..3
    gWq[o] = W_tree[e * 256 + 4 * kp2 + q];
}

// packed fp32x2 FMA (Blackwell)
__device__ __forceinline__ float2 ffma2(float2 a, float2 b, float2 c) {
    unsigned long long ua, ub, uc, ud;
    ua = *reinterpret_cast<unsigned long long*>(&a);
    ub = *reinterpret_cast<unsigned long long*>(&b);
    uc = *reinterpret_cast<unsigned long long*>(&c);
    asm("fma.rn.f32x2 %0, %1, %2, %3;" : "=l"(ud) : "l"(ua), "l"(ub), "l"(uc));
    return *reinterpret_cast<float2*>(&ud);
}

// SMEM layout (floats):
//   sWq  [32768]  = 131072 B
//   bufA [16384]  =  65536 B   (128 nodes x 128)
//   bufB [ 8192]  =  32768 B   ( 64 nodes x 128)
//   sb   [  128]  =    512 B
// total = 229888 B
#define SMEM_FLOATS (32768 + 16384 + 8192 + 128)
#define SMEM_BYTES  (SMEM_FLOATS * 4)

// One tree level. Thread owns features (e2, e2+64) and up to JC nodes
// n = grp + 8*j. in4: input buffer (2*nodesOut nodes x 128 fl = nodesOut x 64 float4
// per node-pair). wq4: repacked W. active: this thread's grp has a node.
template<int JC>
__device__ __forceinline__ void level_compute(const float4* __restrict__ in4,
                                              float* __restrict__ outb,
                                              const float4* __restrict__ wq4,
                                              const float* __restrict__ sb,
                                              int e2, int grp, bool active)
{
    float2 acc0[JC], acc1[JC];
    #pragma unroll
    for (int j = 0; j < JC; j++) {
        acc0[j] = make_float2(0.f, 0.f);
        acc1[j] = make_float2(0.f, 0.f);
    }

    if (active) {
        const float4* w0p = wq4 + e2;        // [kp2*128 + e2]
        const float4* w1p = wq4 + e2 + 64;   // [kp2*128 + e2+64]

        #pragma unroll 2
        for (int kp2 = 0; kp2 < 64; kp2++) {
            float4 w0 = w0p[kp2 * 128];
            float4 w1 = w1p[kp2 * 128];
            #pragma unroll
            for (int j = 0; j < JC; j++) {
                int n = grp + 8 * j;
                float4 x = in4[n * 64 + kp2];   // broadcast across warp
                float2 xa = make_float2(x.x, x.y);
                float2 xb = make_float2(x.z, x.w);
                acc0[j] = ffma2(xa, make_float2(w0.x, w0.y), acc0[j]);
                acc0[j] = ffma2(xb, make_float2(w0.z, w0.w), acc0[j]);
                acc1[j] = ffma2(xa, make_float2(w1.x, w1.y), acc1[j]);
                acc1[j] = ffma2(xb, make_float2(w1.z, w1.w), acc1[j]);
            }
        }

        const float b0 = sb[e2];
        const float b1 = sb[e2 + 64];
        #pragma unroll
        for (int j = 0; j < JC; j++) {
            int n = grp + 8 * j;
            outb[n * 128 + e2]      = tanhf(acc0[j].x + acc0[j].y + b0);
            outb[n * 128 + e2 + 64] = tanhf(acc1[j].x + acc1[j].y + b1);
        }
    }
}

__global__ __launch_bounds__(NTHREADS, 1)
void tree_kernel(const int* __restrict__ tokens,
                 const float* __restrict__ embedding,
                 const float* __restrict__ b_tree,
                 const float* __restrict__ W_cls,
                 const float* __restrict__ b_cls,
                 float* __restrict__ out)
{
    extern __shared__ float smem[];
    float* sWq  = smem;
    float* bufA = smem + 32768;
    float* bufB = bufA + 16384;
    float* sb   = bufB + 8192;

    const int t = threadIdx.x;

    // --- Load repacked W into SMEM (vectorized, conflict-free) ---
    {
        float4* d4 = reinterpret_cast<float4*>(sWq);
        const float4* s4 = reinterpret_cast<const float4*>(gWq);
        #pragma unroll 4
        for (int i = t; i < 8192; i += NTHREADS) d4[i] = s4[i];
    }
    if (t < 128) sb[t] = b_tree[t];

    const int e2  = t & 63;    // feature pair: owns e2 and e2+64
    const int grp = t >> 6;    // node group 0..7

    const float4* wq4 = reinterpret_cast<const float4*>(sWq);

    for (int r = 0; r < ROWS_PB; r++) {
        const int row = blockIdx.x * ROWS_PB + r;

        // --- Phase 1: embedding gather into bufA (128 leaves x 128) ---
        {
            float4* bA4 = reinterpret_cast<float4*>(bufA);
            const float4* emb4 = reinterpret_cast<const float4*>(embedding);
            const int* trow = tokens + row * SEQ_L;
            #pragma unroll 4
            for (int i = t; i < 4096; i += NTHREADS) {
                int leaf = i >> 5;
                int c4   = i & 31;
                int tok = trow[leaf];
                tok = min(max(tok, 0), VOCAB - 1);   // insurance clamp
                bA4[i] = emb4[(long long)tok * 32 + c4];
            }
        }
        __syncthreads();

        // --- Phase 2: 7 tree levels (ping-pong bufA/bufB) ---
        // L0: 64 nodes (JC=8)  L1: 32 (JC=4)  L2: 16 (JC=2)  L3: 8 (JC=1)
        // L4: 4  L5: 2  L6: 1  (JC=1, grp-guarded)
        {
            const float4* inA = reinterpret_cast<const float4*>(bufA);
            const float4* inB = reinterpret_cast<const float4*>(bufB);

            level_compute<8>(inA, bufB, wq4, sb, e2, grp, true);
            __syncthreads();
            level_compute<4>(inB, bufA, wq4, sb, e2, grp, true);
            __syncthreads();
            level_compute<2>(inA, bufB, wq4, sb, e2, grp, true);
            __syncthreads();
            level_compute<1>(inB, bufA, wq4, sb, e2, grp, true);
            __syncthreads();
            level_compute<1>(inA, bufB, wq4, sb, e2, grp, grp < 4);
            __syncthreads();
            level_compute<1>(inB, bufA, wq4, sb, e2, grp, grp < 2);
            __syncthreads();
            level_compute<1>(inA, bufB, wq4, sb, e2, grp, grp < 1);
            __syncthreads();
        }
        // Root reps (128 floats) are at bufB[0..127].

        // --- Phase 3: classifier: out[row] = root @ W_cls^T + b_cls ---
        if (t < 96) {
            int j = t >> 5, lane = t & 31;
            const float* wrow = W_cls + j * 128;
            float p = bufB[lane]       * wrow[lane]
                    + bufB[lane + 32]  * wrow[lane + 32]
                    + bufB[lane + 64]  * wrow[lane + 64]
                    + bufB[lane + 96]  * wrow[lane + 96];
            #pragma unroll
            for (int off = 16; off; off >>= 1)
                p += __shfl_down_sync(0xffffffffu, p, off);
            if (lane == 0) out[row * OUT_N + j] = p + b_cls[j];
        }
        __syncthreads();   // protect buffers before next row
    }
}

extern "C" void kernel_launch(void* const* d_in, const int* in_sizes, int n_in,
                              void* d_out, int out_size) {
    const int*   tokens    = (const int*)d_in[0];
    const float* embedding = (const float*)d_in[1];
    const float* W_tree    = (const float*)d_in[2];
    const float* b_tree    = (const float*)d_in[3];
    const float* W_cls     = (const float*)d_in[4];
    const float* b_cls     = (const float*)d_in[5];
    float*       out       = (float*)d_out;

    (void)in_sizes; (void)n_in; (void)out_size;

    prep_wq_kernel<<<128, 256>>>(W_tree);

    cudaFuncSetAttribute(tree_kernel,
                         cudaFuncAttributeMaxDynamicSharedMemorySize, SMEM_BYTES);

    tree_kernel<<<B_ROWS / ROWS_PB, NTHREADS, SMEM_BYTES>>>(
        tokens, embedding, b_tree, W_cls, b_cls, out);
}

// round 9
// speedup vs baseline: 1.5152x; 1.0373x over previous
#include <cuda_runtime.h>
#include <cstdint>

// Problem constants
#define B_ROWS   4096
#define SEQ_L    128
#define VOCAB    100000
#define OUT_N    3
#define ROWS_PB  4
#define NTHREADS 512

// Repacked W_tree as float4 tiles:
// Wq[kp2*128 + e] (float4) = (W[e][4kp2], W[e][4kp2+1], W[e][4kp2+2], W[e][4kp2+3])
__device__ float gWq[128 * 256];

__global__ void prep_wq_kernel(const float* __restrict__ W_tree) {
    int o = blockIdx.x * 256 + threadIdx.x;   // 0 .. 32767
    int kp2 = o >> 9;          // 0..63
    int rem = o & 511;
    int e   = rem >> 2;        // 0..127
    int q   = rem & 3;         // 0..3
    gWq[o] = W_tree[e * 256 + 4 * kp2 + q];
}

// packed fp32x2 FMA (Blackwell)
__device__ __forceinline__ float2 ffma2(float2 a, float2 b, float2 c) {
    unsigned long long ua, ub, uc, ud;
    ua = *reinterpret_cast<unsigned long long*>(&a);
    ub = *reinterpret_cast<unsigned long long*>(&b);
    uc = *reinterpret_cast<unsigned long long*>(&c);
    asm("fma.rn.f32x2 %0, %1, %2, %3;" : "=l"(ud) : "l"(ua), "l"(ub), "l"(uc));
    return *reinterpret_cast<float2*>(&ud);
}

// SMEM (floats): sWq 32768 | nodes 8192 | scratch 8192 | sb 128 | stok 128(int)
// bytes = 131072 + 32768 + 32768 + 512 + 512 = 197632
#define SMEM_FLOATS (32768 + 8192 + 8192 + 128 + 128)
#define SMEM_BYTES  (SMEM_FLOATS * 4)

// ---------------- Level 0: fused embedding gather, 64 output nodes, JC=8 ----
__device__ __forceinline__ void level0(const float4* __restrict__ emb4,
                                       const int* __restrict__ stok,
                                       float* __restrict__ nodes,
                                       const float4* __restrict__ wq4,
                                       const float* __restrict__ sb,
                                       int e2, int grp)
{
    float2 acc0[8], acc1[8];
    #pragma unroll
    for (int j = 0; j < 8; j++) {
        acc0[j] = make_float2(0.f, 0.f);
        acc1[j] = make_float2(0.f, 0.f);
    }

    const float4* w0p = wq4 + e2;
    const float4* w1p = wq4 + e2 + 64;

    int off[8];
    // left children (k < 128)
    #pragma unroll
    for (int j = 0; j < 8; j++) {
        int tok = stok[2 * (grp + 8 * j)];
        tok = min(max(tok, 0), VOCAB - 1);
        off[j] = tok * 32;
    }
    #pragma unroll 2
    for (int c = 0; c < 32; c++) {
        float4 w0 = w0p[c * 128];
        float4 w1 = w1p[c * 128];
        #pragma unroll
        for (int j = 0; j < 8; j++) {
            float4 x = __ldg(&emb4[off[j] + c]);
            float2 xa = make_float2(x.x, x.y);
            float2 xb = make_float2(x.z, x.w);
            acc0[j] = ffma2(xa, make_float2(w0.x, w0.y), acc0[j]);
            acc0[j] = ffma2(xb, make_float2(w0.z, w0.w), acc0[j]);
            acc1[j] = ffma2(xa, make_float2(w1.x, w1.y), acc1[j]);
            acc1[j] = ffma2(xb, make_float2(w1.z, w1.w), acc1[j]);
        }
    }
    // right children (k >= 128)
    #pragma unroll
    for (int j = 0; j < 8; j++) {
        int tok = stok[2 * (grp + 8 * j) + 1];
        tok = min(max(tok, 0), VOCAB - 1);
        off[j] = tok * 32;
    }
    #pragma unroll 2
    for (int c = 32; c < 64; c++) {
        float4 w0 = w0p[c * 128];
        float4 w1 = w1p[c * 128];
        #pragma unroll
        for (int j = 0; j < 8; j++) {
            float4 x = __ldg(&emb4[off[j] + (c - 32)]);
            float2 xa = make_float2(x.x, x.y);
            float2 xb = make_float2(x.z, x.w);
            acc0[j] = ffma2(xa, make_float2(w0.x, w0.y), acc0[j]);
            acc0[j] = ffma2(xb, make_float2(w0.z, w0.w), acc0[j]);
            acc1[j] = ffma2(xa, make_float2(w1.x, w1.y), acc1[j]);
            acc1[j] = ffma2(xb, make_float2(w1.z, w1.w), acc1[j]);
        }
    }

    const float b0 = sb[e2];
    const float b1 = sb[e2 + 64];
    #pragma unroll
    for (int j = 0; j < 8; j++) {
        int n = grp + 8 * j;
        nodes[n * 128 + e2]      = tanhf(acc0[j].x + acc0[j].y + b0);
        nodes[n * 128 + e2 + 64] = tanhf(acc1[j].x + acc1[j].y + b1);
    }
}

// ---------------- Split-k partial phase for levels 1..6 ---------------------
// NOUT output nodes. 8 groups = NG node-subgroups x S k-slices. Group handles
// J = NOUT/NG nodes over kp2 slice [s*64/S, (s+1)*64/S). Inputs: compact slots
// 0..2*NOUT-1 of nodes[]. Partials (no bias/tanh) -> scratch[(s*NOUT+n)*128+e].
template<int NOUT, int NG, int S, int J>
__device__ __forceinline__ void level_partial(const float4* __restrict__ nodes4,
                                              float* __restrict__ scratch,
                                              const float4* __restrict__ wq4,
                                              int e2, int grp)
{
    const int ng2 = grp % NG;
    const int s   = grp / NG;
    constexpr int KP = 64 / S;            // kp2 per slice (<= 32, half-aligned)
    const int kp2_0 = s * KP;
    const int side  = (kp2_0 >= 32) ? 1 : 0;  // left/right child
    const int col0  = kp2_0 - side * 32;

    float2 acc0[J], acc1[J];
    #pragma unroll
    for (int j = 0; j < J; j++) {
        acc0[j] = make_float2(0.f, 0.f);
        acc1[j] = make_float2(0.f, 0.f);
    }

    const float4* w0p = wq4 + kp2_0 * 128 + e2;
    const float4* w1p = w0p + 64;

    #pragma unroll 2
    for (int c = 0; c < KP; c++) {
        float4 w0 = w0p[c * 128];
        float4 w1 = w1p[c * 128];
        #pragma unroll
        for (int j = 0; j < J; j++) {
            int n = ng2 + NG * j;
            float4 x = nodes4[(2 * n + side) * 32 + col0 + c];  // warp-broadcast
            float2 xa = make_float2(x.x, x.y);
            float2 xb = make_float2(x.z, x.w);
            acc0[j] = ffma2(xa, make_float2(w0.x, w0.y), acc0[j]);
            acc0[j] = ffma2(xb, make_float2(w0.z, w0.w), acc0[j]);
            acc1[j] = ffma2(xa, make_float2(w1.x, w1.y), acc1[j]);
            acc1[j] = ffma2(xb, make_float2(w1.z, w1.w), acc1[j]);
        }
    }

    #pragma unroll
    for (int j = 0; j < J; j++) {
        int n = ng2 + NG * j;
        float* p = scratch + (s * NOUT + n) * 128;
        p[e2]      = acc0[j].x + acc0[j].y;
        p[e2 + 64] = acc1[j].x + acc1[j].y;
    }
}

// Reduce S partials, add bias, tanh, write outputs compact to slots 0..NOUT-1.
template<int NOUT, int S>
__device__ __forceinline__ void level_reduce(float* __restrict__ nodes,
                                             const float* __restrict__ scratch,
                                             const float* __restrict__ sb, int t)
{
    for (int v = t; v < NOUT * 128; v += NTHREADS) {
        float sum = sb[v & 127];
        #pragma unroll
        for (int s = 0; s < S; s++) sum += scratch[s * NOUT * 128 + v];
        nodes[v] = tanhf(sum);
    }
}

__global__ __launch_bounds__(NTHREADS, 1)
void tree_kernel(const int* __restrict__ tokens,
                 const float* __restrict__ embedding,
                 const float* __restrict__ b_tree,
                 const float* __restrict__ W_cls,
                 const float* __restrict__ b_cls,
                 float* __restrict__ out)
{
    extern __shared__ float smem[];
    float* sWq     = smem;
    float* nodes   = smem + 32768;
    float* scratch = nodes + 8192;
    float* sb      = scratch + 8192;
    int*   stok    = reinterpret_cast<int*>(sb + 128);

    const int t = threadIdx.x;

    // Load repacked W into SMEM (vectorized, conflict-free)
    {
        float4* d4 = reinterpret_cast<float4*>(sWq);
        const float4* s4 = reinterpret_cast<const float4*>(gWq);
        #pragma unroll 4
        for (int i = t; i < 8192; i += NTHREADS) d4[i] = s4[i];
    }
    if (t < 128) sb[t] = b_tree[t];

    const int e2  = t & 63;
    const int grp = t >> 6;
    const float4* wq4    = reinterpret_cast<const float4*>(sWq);
    const float4* nodes4 = reinterpret_cast<const float4*>(nodes);
    const float4* emb4   = reinterpret_cast<const float4*>(embedding);

    for (int r = 0; r < ROWS_PB; r++) {
        const int row = blockIdx.x * ROWS_PB + r;
        if (t < 128) stok[t] = tokens[row * SEQ_L + t];
        __syncthreads();

        // L0: 128 leaves (from gmem/L2) -> 64 nodes
        level0(emb4, stok, nodes, wq4, sb, e2, grp);
        __syncthreads();

        // L1..L6 via split-k partial + reduce
        level_partial<32, 4, 2, 8>(nodes4, scratch, wq4, e2, grp); __syncthreads();
        level_reduce<32, 2>(nodes, scratch, sb, t);                __syncthreads();
        level_partial<16, 2, 4, 8>(nodes4, scratch, wq4, e2, grp); __syncthreads();
        level_reduce<16, 4>(nodes, scratch, sb, t);                __syncthreads();
        level_partial<8, 1, 8, 8>(nodes4, scratch, wq4, e2, grp);  __syncthreads();
        level_reduce<8, 8>(nodes, scratch, sb, t);                 __syncthreads();
        level_partial<4, 1, 8, 4>(nodes4, scratch, wq4, e2, grp);  __syncthreads();
        level_reduce<4, 8>(nodes, scratch, sb, t);                 __syncthreads();
        level_partial<2, 1, 8, 2>(nodes4, scratch, wq4, e2, grp);  __syncthreads();
        level_reduce<2, 8>(nodes, scratch, sb, t);                 __syncthreads();
        level_partial<1, 1, 8, 1>(nodes4, scratch, wq4, e2, grp);  __syncthreads();
        level_reduce<1, 8>(nodes, scratch, sb, t);                 __syncthreads();

        // Classifier: root reps at nodes[0..127]
        if (t < 96) {
            int j = t >> 5, lane = t & 31;
            const float* wrow = W_cls + j * 128;
            float p = nodes[lane]       * wrow[lane]
                    + nodes[lane + 32]  * wrow[lane + 32]
                    + nodes[lane + 64]  * wrow[lane + 64]
                    + nodes[lane + 96]  * wrow[lane + 96];
            #pragma unroll
            for (int off = 16; off; off >>= 1)
                p += __shfl_down_sync(0xffffffffu, p, off);
            if (lane == 0) out[row * OUT_N + j] = p + b_cls[j];
        }
        __syncthreads();   // protect nodes/stok before next row
    }
}

extern "C" void kernel_launch(void* const* d_in, const int* in_sizes, int n_in,
                              void* d_out, int out_size) {
    const int*   tokens    = (const int*)d_in[0];
    const float* embedding = (const float*)d_in[1];
    const float* W_tree    = (const float*)d_in[2];
    const float* b_tree    = (const float*)d_in[3];
    const float* W_cls     = (const float*)d_in[4];
    const float* b_cls     = (const float*)d_in[5];
    float*       out       = (float*)d_out;

    (void)in_sizes; (void)n_in; (void)out_size;

    prep_wq_kernel<<<128, 256>>>(W_tree);

    cudaFuncSetAttribute(tree_kernel,
                         cudaFuncAttributeMaxDynamicSharedMemorySize, SMEM_BYTES);

    tree_kernel<<<B_ROWS / ROWS_PB, NTHREADS, SMEM_BYTES>>>(
        tokens, embedding, b_tree, W_cls, b_cls, out);
}